// round 12
// baseline (speedup 1.0000x reference)
#include <cuda_runtime.h>
#include <cuda_fp16.h>
#include <cstdint>

#define SEQ 512
#define DIN 512
#define MEM 256
#define HID 512
#define NBATCH 64
#define URPAD 640

#define RSB 144                  // row stride bytes: 64 fp16 = 128 B + 16 pad
#define TILEB (128 * RSB)        // 18432 B
#define BUFB (2 * TILEB)         // A, B tiles
#define SMEM_DYN (3 * BUFB)      // 3-stage pipeline: 110592 B

#define CHAIN_GRID 256
#define XS_PITCH 260

// ---------------- static device scratch ----------------
__device__ __align__(16) __half g_xh[NBATCH * SEQ * DIN];
__device__ __align__(16) __half g_urh[NBATCH * URPAD];
__device__ __align__(16) __half g_toep[NBATCH * 8 * 128 * 64];  // 8 canonical tiles/batch
__device__ __align__(16) __half g_wht[HID * DIN];    // Wht[j][k] = Wh[256+k][j]
__device__ __align__(16) __half g_gt[HID * SEQ];     // Gt[j][d] = G[d][j]
__device__ float g_Ht[SEQ * MEM];
__device__ float g_AT[2][MEM * MEM];
__device__ unsigned g_count;   // zero at load; reset by k_main tail each run
__device__ unsigned g_epoch;

// ---------------- helpers ----------------
__device__ __forceinline__ uint32_t smem_to_u32(const void* p) {
    uint32_t a;
    asm("{ .reg .u64 t; cvta.to.shared.u64 t, %1; cvt.u32.u64 %0, t; }" : "=r"(a) : "l"(p));
    return a;
}
__device__ __forceinline__ void cp16(uint32_t dst, const void* src) {
    asm volatile("cp.async.cg.shared.global [%0], [%1], 16;" :: "r"(dst), "l"(src));
}
#define CP_COMMIT() asm volatile("cp.async.commit_group;" ::: "memory")
#define CP_WAIT(n)  asm volatile("cp.async.wait_group %0;" :: "n"(n) : "memory")

__device__ __forceinline__ void ldsm4(uint32_t r[4], uint32_t addr) {
    asm volatile("ldmatrix.sync.aligned.m8n8.x4.shared.b16 {%0,%1,%2,%3}, [%4];"
                 : "=r"(r[0]), "=r"(r[1]), "=r"(r[2]), "=r"(r[3]) : "r"(addr));
}
__device__ __forceinline__ void mma_f16(float* c, const uint32_t* a, const uint32_t* b) {
    asm volatile(
        "mma.sync.aligned.m16n8k16.row.col.f32.f16.f16.f32 "
        "{%0,%1,%2,%3}, {%4,%5,%6,%7}, {%8,%9}, {%0,%1,%2,%3};"
        : "+f"(c[0]), "+f"(c[1]), "+f"(c[2]), "+f"(c[3])
        : "r"(a[0]), "r"(a[1]), "r"(a[2]), "r"(a[3]), "r"(b[0]), "r"(b[1]));
}

// grid barrier among chain blocks: arrive via atomic, wait via acquire-load poll
__device__ __forceinline__ void grid_barrier(int bar) {
    __threadfence();
    __syncthreads();
    if (threadIdx.x == 0) {
        unsigned my = atomicAdd(&g_count, 1u);
        if (my == (unsigned)(CHAIN_GRID * bar - 1)) {
            atomicAdd(&g_epoch, 1u);
        } else {
            while (true) {
                unsigned e;
                asm volatile("ld.global.acquire.gpu.b32 %0, [%1];" : "=r"(e) : "l"(&g_epoch));
                if (e >= (unsigned)bar) break;
                __nanosleep(64);
            }
        }
    }
    __syncthreads();
}

// ---------------- k_ux: u = relu(x@Wu+b) + fp16 x, one pass ----------------
__global__ __launch_bounds__(256) void k_ux(const float* __restrict__ x,
                                            const float* __restrict__ wu,
                                            const float* __restrict__ wub) {
    int row = blockIdx.x * 8 + (threadIdx.x >> 5);   // [0, 32768)
    int lane = threadIdx.x & 31;
    const float4* xr = (const float4*)(x + (size_t)row * DIN);
    const float4* wr = (const float4*)wu;
    float s = 0.f;
#pragma unroll
    for (int i = 0; i < 4; i++) {
        float4 v = xr[lane + 32 * i];
        float4 w = wr[lane + 32 * i];
        s += v.x * w.x + v.y * w.y + v.z * w.z + v.w * w.w;
        size_t off = (size_t)row * DIN + (lane + 32 * i) * 4;
        __half2 ha = {__float2half(v.x), __float2half(v.y)};
        __half2 hb = {__float2half(v.z), __float2half(v.w)};
        *(__half2*)(g_xh + off) = ha; *(__half2*)(g_xh + off + 2) = hb;
    }
#pragma unroll
    for (int o = 16; o; o >>= 1) s += __shfl_xor_sync(0xffffffffu, s, o);
    if (lane == 0) {
        float u = fmaxf(s + wub[0], 0.f);
        int b = row >> 9, t = row & 511;
        g_urh[b * URPAD + (511 - t)] = __float2half(u);
        if (t < 128) g_urh[b * URPAD + 512 + t] = __float2half(0.f);
    }
}

// ---------------- k_toep: 8 canonical Toeplitz tiles per batch ----------------
// tile[kidx](r,c) = ur[575 - 64*kidx - r + c], r in [0,128), c in [0,64)
__global__ __launch_bounds__(256) void k_toep() {
    __shared__ uint32_t urs[320];
    int blk = blockIdx.x;                 // b*8 + kidx
    int b = blk >> 3, kidx = blk & 7;
    for (int q = threadIdx.x; q < 320; q += 256)
        urs[q] = ((const uint32_t*)(g_urh + (size_t)b * URPAD))[q];
    __syncthreads();
    int r = threadIdx.x >> 1, hf = threadIdx.x & 1;
    int s0 = 575 - 64 * kidx - r + hf * 32;
    int base = s0 >> 1, par = s0 & 1;
    uint32_t w[16];
    uint32_t w0 = urs[base];
#pragma unroll
    for (int c = 0; c < 16; c++) {
        uint32_t w1 = urs[base + c + 1];
        w[c] = par ? __byte_perm(w0, w1, 0x5432) : w0;
        w0 = w1;
    }
    __half* dst = g_toep + (size_t)blk * 8192 + r * 64 + hf * 32;
#pragma unroll
    for (int q = 0; q < 4; q++)
        *(uint4*)(dst + q * 8) = make_uint4(w[q * 4], w[q * 4 + 1], w[q * 4 + 2], w[q * 4 + 3]);
}

// ---------------- k_chain: wt + A^T init + 9 doubling rounds + G ----------------
__global__ __launch_bounds__(256) void k_chain(const float* __restrict__ Wh,
                                               const float* __restrict__ A,
                                               const float* __restrict__ Bv) {
    __shared__ float Xs[16 * XS_PITCH];
    __shared__ float Bs[256 * 16];
    const int bid = blockIdx.x, tid = threadIdx.x;
    const int ty = tid >> 4, tx = tid & 15;

    // init: A^T column bid; block 0 also Ht[0]=B; plus one 32x32 wht tile
    g_AT[0][(size_t)bid * MEM + tid] = A[(size_t)tid * MEM + bid];
    if (bid == 0) g_Ht[tid] = Bv[tid];
    {
        float (*tile)[33] = (float (*)[33])Xs;
        int kb = bid & 15, jb = bid >> 4;
        int ttx = tid & 31, tty = tid >> 5;
        for (int yy = tty; yy < 32; yy += 8)
            tile[yy][ttx] = Wh[(size_t)(MEM + kb * 32 + yy) * HID + jb * 32 + ttx];
        __syncthreads();
        for (int yy = tty; yy < 32; yy += 8) {
            float v = tile[ttx][yy];
            int j = jb * 32 + yy, k = kb * 32 + ttx;
            g_wht[(size_t)j * DIN + k] = __float2half(v);
        }
    }
    grid_barrier(1);

    for (int r = 0; r <= 8; r++) {
        int n = 1 << r;
        int sel = r & 1;
        int nsq = (r < 8) ? 256 : 0;             // 16x16 squaring tiles
        int nrt = (n + 15) / 16;
        int ntiles = nsq + nrt * 16;
        const float* __restrict__ ATin = g_AT[sel];
        for (int t = bid; t < ntiles; t += CHAIN_GRID) {
            const float* Amat; float* Cmat; int rows, tr, tc;
            if (t < nsq) { Amat = ATin; Cmat = g_AT[sel ^ 1]; rows = MEM; tr = t >> 4; tc = t & 15; }
            else { int te = t - nsq; Amat = g_Ht; Cmat = g_Ht + (size_t)n * MEM; rows = n; tr = te >> 4; tc = te & 15; }
            int r0 = tr * 16, c0 = tc * 16;
            __syncthreads();
            for (int q = tid; q < 1024; q += 256) {
                int row = q >> 6, c4 = (q & 63) * 4;
                float4 v = make_float4(0.f, 0.f, 0.f, 0.f);
                if (r0 + row < rows) v = *(const float4*)(Amat + (size_t)(r0 + row) * MEM + c4);
                *(float4*)&Xs[row * XS_PITCH + c4] = v;
                int brow = q >> 2, bc4 = (q & 3) * 4;
                *(float4*)&Bs[brow * 16 + bc4] = *(const float4*)(ATin + (size_t)brow * MEM + c0 + bc4);
            }
            __syncthreads();
            float acc = 0.f;
#pragma unroll 16
            for (int k = 0; k < MEM; k++)
                acc = fmaf(Xs[ty * XS_PITCH + k], Bs[k * 16 + tx], acc);
            if (r0 + ty < rows) Cmat[(size_t)(r0 + ty) * MEM + c0 + tx] = acc;
        }
        grid_barrier(r + 2);
    }

    // G phase: G = Ht @ Wh_m -> gt[j][d] fp16 (1024 tiles of 16x16)
    for (int t = bid; t < 1024; t += CHAIN_GRID) {
        int tr = t >> 5, tc = t & 31;
        int d0 = tr * 16, j0 = tc * 16;
        __syncthreads();
        for (int q = tid; q < 1024; q += 256) {
            int row = q >> 6, c4 = (q & 63) * 4;
            *(float4*)&Xs[row * XS_PITCH + c4] = *(const float4*)(g_Ht + (size_t)(d0 + row) * MEM + c4);
            int brow = q >> 2, bc4 = (q & 3) * 4;
            *(float4*)&Bs[brow * 16 + bc4] = *(const float4*)(Wh + (size_t)brow * HID + j0 + bc4);
        }
        __syncthreads();
        float acc = 0.f;
#pragma unroll 16
        for (int k = 0; k < MEM; k++)
            acc = fmaf(Xs[ty * XS_PITCH + k], Bs[k * 16 + tx], acc);
        g_gt[(size_t)(j0 + tx) * SEQ + d0 + ty] = __float2half(acc);
    }
}

// ---------------- k_main: single-product fp16 fused GEMM, 3-stage pipeline ----------------
__device__ __forceinline__ void cp_tile64(uint32_t sdst, const __half* __restrict__ g,
                                          int stride, int tid) {
#pragma unroll
    for (int it = 0; it < 4; it++) {
        int q = tid + it * 256;
        int row = q >> 3, ch = q & 7;
        cp16(sdst + row * RSB + ch * 16, g + (size_t)row * stride + ch * 8);
    }
}

__global__ __launch_bounds__(256, 2) void k_main(const float* __restrict__ Whb,
                                                 float* __restrict__ out, int write_hn) {
    extern __shared__ __align__(128) char smem[];
    const int b = blockIdx.z;
    const int by = blockIdx.y;
    const int t0 = by * 128;
    const int j0 = blockIdx.x * 128;
    const int tid = threadIdx.x;
    const int lane = tid & 31;
    const int warp_m = (tid >> 5) & 1;
    const int warp_n = tid >> 6;
    const uint32_t sbase = smem_to_u32(smem);

    const __half* xh = g_xh + ((size_t)(b * SEQ + t0)) * DIN;
    const __half* wt = g_wht + (size_t)j0 * DIN;
    const __half* gt = g_gt + (size_t)j0 * SEQ;
    const __half* tp = g_toep + (size_t)b * 8 * 8192;

    const int nchunks = 10 + 2 * by;   // 8 dense + (2*by+2) toeplitz

    auto fill = [&](int i, int p) {
        uint32_t sb = sbase + p * BUFB;
        if (i < 8) {
            int k0 = i * 64;
            cp_tile64(sb,         xh + k0, DIN, tid);
            cp_tile64(sb + TILEB, wt + k0, DIN, tid);
        } else {
            int d0 = (i - 8) * 64;
            int kidx = 2 * by - (i - 8) + 1;
            cp_tile64(sb,         tp + (size_t)kidx * 8192, 64, tid);
            cp_tile64(sb + TILEB, gt + d0, SEQ, tid);
        }
    };

    float acc[4][4][4];
#pragma unroll
    for (int mi = 0; mi < 4; mi++)
#pragma unroll
        for (int ni = 0; ni < 4; ni++)
#pragma unroll
            for (int e = 0; e < 4; e++) acc[mi][ni][e] = 0.f;

    fill(0, 0); CP_COMMIT();
    fill(1, 1); CP_COMMIT();

    const uint32_t a_base_off = (warp_m * 64 + (lane & 15)) * RSB + ((lane >> 4) << 4);
    const uint32_t b_base_off = TILEB + (warp_n * 32 + (lane & 15)) * RSB + ((lane >> 4) << 4);

    for (int i = 0; i < nchunks; i++) {
        int p = i % 3;
        if (i + 2 < nchunks) { fill(i + 2, (i + 2) % 3); CP_COMMIT(); CP_WAIT(2); }
        else if (i + 1 < nchunks) { CP_WAIT(1); }
        else { CP_WAIT(0); }
        __syncthreads();

        uint32_t base = sbase + p * BUFB;
#pragma unroll
        for (int ks = 0; ks < 4; ks++) {
            uint32_t bh[4][2];
            {
                uint32_t r[4];
                uint32_t baddr = base + b_base_off + ks * 32;
                ldsm4(r, baddr);
                bh[0][0] = r[0]; bh[0][1] = r[2];
                bh[1][0] = r[1]; bh[1][1] = r[3];
                ldsm4(r, baddr + 16 * RSB);
                bh[2][0] = r[0]; bh[2][1] = r[2];
                bh[3][0] = r[1]; bh[3][1] = r[3];
            }
            uint32_t a[4][4];
            uint32_t aaddr = base + a_base_off + ks * 32;
#pragma unroll
            for (int mi = 0; mi < 4; mi++) ldsm4(a[mi], aaddr + mi * 16 * RSB);
#pragma unroll
            for (int mi = 0; mi < 4; mi++)
#pragma unroll
                for (int ni = 0; ni < 4; ni++)
                    mma_f16(acc[mi][ni], a[mi], bh[ni]);
        }
        __syncthreads();
    }

    // ---- epilogue ----
    const int g4 = lane >> 2, t4 = lane & 3;
    const size_t HN_BASE = (size_t)NBATCH * SEQ * HID;
    float2 bias[4];
#pragma unroll
    for (int ni = 0; ni < 4; ni++)
        bias[ni] = *(const float2*)(Whb + j0 + warp_n * 32 + ni * 8 + t4 * 2);
#pragma unroll
    for (int mi = 0; mi < 4; mi++) {
        int ta = t0 + warp_m * 64 + mi * 16 + g4;
        int tb = ta + 8;
        size_t rowa = ((size_t)b * SEQ + ta) * HID;
        size_t rowb = ((size_t)b * SEQ + tb) * HID;
#pragma unroll
        for (int ni = 0; ni < 4; ni++) {
            int j = j0 + warp_n * 32 + ni * 8 + t4 * 2;
            float2 v0, v1;
            v0.x = fmaxf(acc[mi][ni][0] + bias[ni].x, 0.f);
            v0.y = fmaxf(acc[mi][ni][1] + bias[ni].y, 0.f);
            v1.x = fmaxf(acc[mi][ni][2] + bias[ni].x, 0.f);
            v1.y = fmaxf(acc[mi][ni][3] + bias[ni].y, 0.f);
            *(float2*)(out + rowa + j) = v0;
            *(float2*)(out + rowb + j) = v1;
            if (write_hn && tb == SEQ - 1)
                *(float2*)(out + HN_BASE + (size_t)b * HID + j) = v1;
        }
    }

    // reset chain-barrier state for the next replay (zero at load; zeroed after
    // every k_main so every launch sequence sees identical state)
    if (blockIdx.x == 0 && blockIdx.y == 0 && blockIdx.z == 0 && tid == 0) {
        g_count = 0;
        g_epoch = 0;
    }
}

// ---------------- launch ----------------
extern "C" void kernel_launch(void* const* d_in, const int* in_sizes, int n_in,
                              void* d_out, int out_size) {
    const float* x    = (const float*)d_in[0];
    const float* Wu_w = (const float*)d_in[1];
    const float* Wu_b = (const float*)d_in[2];
    const float* Wh_w = (const float*)d_in[3];
    const float* Wh_b = (const float*)d_in[4];
    const float* A    = (const float*)d_in[5];
    const float* B    = (const float*)d_in[6];
    float* out = (float*)d_out;

    int write_hn = (out_size >= NBATCH * SEQ * HID + NBATCH * HID) ? 1 : 0;

    static int inited = 0;
    if (!inited) {
        cudaFuncSetAttribute(k_main, cudaFuncAttributeMaxDynamicSharedMemorySize, SMEM_DYN);
        inited = 1;
    }

    k_ux<<<NBATCH * SEQ / 8, 256>>>(x, Wu_w, Wu_b);
    k_toep<<<NBATCH * 8, 256>>>();
    k_chain<<<CHAIN_GRID, 256>>>(Wh_w, A, B);
    k_main<<<dim3(HID / 128, SEQ / 128, NBATCH), 256, SMEM_DYN>>>(Wh_b, out, write_hn);
}

// round 13
// speedup vs baseline: 1.1754x; 1.1754x over previous
#include <cuda_runtime.h>
#include <cuda_fp16.h>
#include <cstdint>

#define SEQ 512
#define DIN 512
#define MEM 256
#define HID 512
#define NBATCH 64
#define URPAD 640

#define RSB 144                  // row stride bytes: 64 fp16 = 128 B + 16 pad
#define TILEB (128 * RSB)        // 18432 B
#define BUFB (2 * TILEB)         // A, B tiles
#define URS_OFF (2 * BUFB)
#define SMEM_DYN (2 * BUFB + 1280)   // 75008 B (chain path needs 66048 <= this)

#define CHAIN_N 128
#define MAIN_BLOCKS 1024
#define FUSED_GRID (CHAIN_N + MAIN_BLOCKS)
#define XS_PITCH 260

// ---------------- static device scratch ----------------
__device__ __align__(16) __half g_xh[NBATCH * SEQ * DIN];
__device__ __align__(16) __half g_urh[NBATCH * URPAD];
__device__ __align__(16) __half g_wht[HID * DIN];    // Wht[j][k] = Wh[256+k][j]
__device__ __align__(16) __half g_gt[HID * SEQ];     // Gt[j][d] = G[d][j]
__device__ float g_Ht[SEQ * MEM];
__device__ float g_AT[2][MEM * MEM];
__device__ unsigned g_count;
__device__ unsigned g_epoch;
__device__ unsigned g_ready;

// ---------------- helpers ----------------
__device__ __forceinline__ uint32_t smem_to_u32(const void* p) {
    uint32_t a;
    asm("{ .reg .u64 t; cvta.to.shared.u64 t, %1; cvt.u32.u64 %0, t; }" : "=r"(a) : "l"(p));
    return a;
}
__device__ __forceinline__ void cp16(uint32_t dst, const void* src) {
    asm volatile("cp.async.cg.shared.global [%0], [%1], 16;" :: "r"(dst), "l"(src));
}
#define CP_COMMIT() asm volatile("cp.async.commit_group;" ::: "memory")
#define CP_WAIT0()  asm volatile("cp.async.wait_group 0;" ::: "memory")
#define CP_WAIT1()  asm volatile("cp.async.wait_group 1;" ::: "memory")

__device__ __forceinline__ void ldsm4(uint32_t r[4], uint32_t addr) {
    asm volatile("ldmatrix.sync.aligned.m8n8.x4.shared.b16 {%0,%1,%2,%3}, [%4];"
                 : "=r"(r[0]), "=r"(r[1]), "=r"(r[2]), "=r"(r[3]) : "r"(addr));
}
__device__ __forceinline__ void mma_f16(float* c, const uint32_t* a, const uint32_t* b) {
    asm volatile(
        "mma.sync.aligned.m16n8k16.row.col.f32.f16.f16.f32 "
        "{%0,%1,%2,%3}, {%4,%5,%6,%7}, {%8,%9}, {%0,%1,%2,%3};"
        : "+f"(c[0]), "+f"(c[1]), "+f"(c[2]), "+f"(c[3])
        : "r"(a[0]), "r"(a[1]), "r"(a[2]), "r"(a[3]), "r"(b[0]), "r"(b[1]));
}

// grid barrier among chain blocks: arrive via atomic, wait via acquire-load poll
__device__ __forceinline__ void grid_barrier(int bar) {
    __threadfence();
    __syncthreads();
    if (threadIdx.x == 0) {
        unsigned my = atomicAdd(&g_count, 1u);
        if (my == (unsigned)(CHAIN_N * bar - 1)) {
            atomicAdd(&g_epoch, 1u);
        } else {
            while (true) {
                unsigned e;
                asm volatile("ld.global.acquire.gpu.b32 %0, [%1];" : "=r"(e) : "l"(&g_epoch));
                if (e >= (unsigned)bar) break;
                __nanosleep(64);
            }
        }
    }
    __syncthreads();
}

// ---------------- k_ux: ux path + wht transpose path; resets sync state ----------------
__global__ __launch_bounds__(256) void k_ux(const float* __restrict__ x,
                                            const float* __restrict__ wu,
                                            const float* __restrict__ wub,
                                            const float* __restrict__ Wh) {
    const int bid = blockIdx.x;
    const int tid = threadIdx.x;
    if (bid == 0 && tid == 0) { g_count = 0; g_epoch = 0; g_ready = 0; }

    if (bid < NBATCH * SEQ / 8) {
        int row = bid * 8 + (tid >> 5);   // [0, 32768)
        int lane = tid & 31;
        const float4* xr = (const float4*)(x + (size_t)row * DIN);
        const float4* wr = (const float4*)wu;
        float s = 0.f;
#pragma unroll
        for (int i = 0; i < 4; i++) {
            float4 v = xr[lane + 32 * i];
            float4 w = wr[lane + 32 * i];
            s += v.x * w.x + v.y * w.y + v.z * w.z + v.w * w.w;
            size_t off = (size_t)row * DIN + (lane + 32 * i) * 4;
            __half2 ha = {__float2half(v.x), __float2half(v.y)};
            __half2 hb = {__float2half(v.z), __float2half(v.w)};
            *(__half2*)(g_xh + off) = ha; *(__half2*)(g_xh + off + 2) = hb;
        }
#pragma unroll
        for (int o = 16; o; o >>= 1) s += __shfl_xor_sync(0xffffffffu, s, o);
        if (lane == 0) {
            float u = fmaxf(s + wub[0], 0.f);
            int b = row >> 9, t = row & 511;
            g_urh[b * URPAD + (511 - t)] = __float2half(u);
            if (t < 128) g_urh[b * URPAD + 512 + t] = __float2half(0.f);
        }
    } else {
        __shared__ float tile[32][33];
        int t = bid - NBATCH * SEQ / 8;            // [0,256)
        int kb = t & 15, jb = t >> 4;
        int tx = tid & 31, ty = tid >> 5;
        for (int yy = ty; yy < 32; yy += 8)
            tile[yy][tx] = Wh[(size_t)(MEM + kb * 32 + yy) * HID + jb * 32 + tx];
        __syncthreads();
        for (int yy = ty; yy < 32; yy += 8) {
            float v = tile[tx][yy];
            int j = jb * 32 + yy, k = kb * 32 + tx;
            g_wht[(size_t)j * DIN + k] = __float2half(v);
        }
    }
}

// ---------------- chain path (device function), runs in blocks [0,128) ----------------
__device__ void chain_path(char* smem, int bid, int tid,
                           const float* __restrict__ Wh,
                           const float* __restrict__ A,
                           const float* __restrict__ Bv) {
    float* Xs = (float*)smem;                  // [32][XS_PITCH]
    float* Bs = Xs + 32 * XS_PITCH;            // [256][32]
    const int ty = tid >> 4, tx = tid & 15;

    // init: block covers 2 columns of A^T; block 0 also Ht[0]=B
    {
        int k0 = bid * 2;
#pragma unroll
        for (int h = 0; h < 2; h++)
            g_AT[0][(size_t)(k0 + h) * MEM + tid] = A[(size_t)tid * MEM + k0 + h];
        if (bid == 0) g_Ht[tid] = Bv[tid];
    }
    grid_barrier(1);

    for (int r = 0; r <= 8; r++) {
        int n = 1 << r;
        int sel = r & 1;
        int nsq = (r < 8) ? 64 : 0;
        int nrt = (n + 31) / 32;
        int ntiles = nsq + nrt * 8;
        const float* __restrict__ ATin = g_AT[sel];
        for (int t = bid; t < ntiles; t += CHAIN_N) {
            const float* Amat; float* Cmat; int rows, tr, tc;
            if (t < nsq) { Amat = ATin; Cmat = g_AT[sel ^ 1]; rows = MEM; tr = t >> 3; tc = t & 7; }
            else { int te = t - nsq; Amat = g_Ht; Cmat = g_Ht + (size_t)n * MEM; rows = n; tr = te >> 3; tc = te & 7; }
            int r0 = tr * 32, c0 = tc * 32;
            __syncthreads();
            for (int q = tid; q < 2048; q += 256) {
                int row = q >> 6, c4 = (q & 63) * 4;
                float4 v = make_float4(0.f, 0.f, 0.f, 0.f);
                if (r0 + row < rows) v = *(const float4*)(Amat + (size_t)(r0 + row) * MEM + c4);
                *(float4*)&Xs[row * XS_PITCH + c4] = v;
                int brow = q >> 3, bc4 = (q & 7) * 4;
                *(float4*)&Bs[brow * 32 + bc4] = *(const float4*)(ATin + (size_t)brow * MEM + c0 + bc4);
            }
            __syncthreads();
            float acc[2][2] = {};
#pragma unroll 8
            for (int k = 0; k < MEM; k++) {
                float a0 = Xs[(ty * 2) * XS_PITCH + k], a1 = Xs[(ty * 2 + 1) * XS_PITCH + k];
                float b0 = Bs[k * 32 + tx * 2],         b1 = Bs[k * 32 + tx * 2 + 1];
                acc[0][0] = fmaf(a0, b0, acc[0][0]); acc[0][1] = fmaf(a0, b1, acc[0][1]);
                acc[1][0] = fmaf(a1, b0, acc[1][0]); acc[1][1] = fmaf(a1, b1, acc[1][1]);
            }
#pragma unroll
            for (int i = 0; i < 2; i++) {
                int rr = r0 + ty * 2 + i;
                if (rr < rows) {
                    Cmat[(size_t)rr * MEM + c0 + tx * 2]     = acc[i][0];
                    Cmat[(size_t)rr * MEM + c0 + tx * 2 + 1] = acc[i][1];
                }
            }
        }
        grid_barrier(r + 2);
    }

    // G phase: G = Ht @ Wh_m -> gt[j][d] fp16 (256 tiles of 32x32)
    for (int t = bid; t < 256; t += CHAIN_N) {
        int tr = t >> 4, tc = t & 15;
        int d0 = tr * 32, j0 = tc * 32;
        __syncthreads();
        for (int q = tid; q < 2048; q += 256) {
            int row = q >> 6, c4 = (q & 63) * 4;
            *(float4*)&Xs[row * XS_PITCH + c4] = *(const float4*)(g_Ht + (size_t)(d0 + row) * MEM + c4);
            int brow = q >> 3, bc4 = (q & 7) * 4;
            *(float4*)&Bs[brow * 32 + bc4] = *(const float4*)(Wh + (size_t)brow * HID + j0 + bc4);
        }
        __syncthreads();
        float acc[2][2] = {};
#pragma unroll 8
        for (int k = 0; k < MEM; k++) {
            float a0 = Xs[(ty * 2) * XS_PITCH + k], a1 = Xs[(ty * 2 + 1) * XS_PITCH + k];
            float b0 = Bs[k * 32 + tx * 2],         b1 = Bs[k * 32 + tx * 2 + 1];
            acc[0][0] = fmaf(a0, b0, acc[0][0]); acc[0][1] = fmaf(a0, b1, acc[0][1]);
            acc[1][0] = fmaf(a1, b0, acc[1][0]); acc[1][1] = fmaf(a1, b1, acc[1][1]);
        }
#pragma unroll
        for (int i = 0; i < 2; i++)
#pragma unroll
            for (int jj = 0; jj < 2; jj++) {
                int d = d0 + ty * 2 + i, j = j0 + tx * 2 + jj;
                g_gt[(size_t)j * SEQ + d] = __float2half(acc[i][jj]);
            }
    }

    // join + release g_ready (last arriver publishes all gt writes)
    __threadfence();
    __syncthreads();
    if (tid == 0) {
        unsigned my = atomicAdd(&g_count, 1u);
        if (my == (unsigned)(CHAIN_N * 11 - 1))
            asm volatile("st.global.release.gpu.b32 [%0], %1;" :: "l"(&g_ready), "r"(1u) : "memory");
    }
}

// ---------------- k_fused: chain blocks + main GEMM blocks, one launch ----------------
__device__ __forceinline__ void cp_tile64(uint32_t sdst, const __half* __restrict__ g,
                                          int stride, int tid) {
#pragma unroll
    for (int it = 0; it < 4; it++) {
        int q = tid + it * 256;
        int row = q >> 3, ch = q & 7;
        cp16(sdst + row * RSB + ch * 16, g + (size_t)row * stride + ch * 8);
    }
}

__global__ __launch_bounds__(256, 2) void k_fused(const float* __restrict__ Wh,
                                                  const float* __restrict__ A,
                                                  const float* __restrict__ Bv,
                                                  const float* __restrict__ Whb,
                                                  float* __restrict__ out, int write_hn) {
    extern __shared__ __align__(128) char smem[];
    const int gbid = blockIdx.x;
    const int tid = threadIdx.x;

    if (gbid < CHAIN_N) {
        chain_path(smem, gbid, tid, Wh, A, Bv);
        return;
    }

    // ---------------- main GEMM path ----------------
    const int idx = gbid - CHAIN_N;          // [0,1024)
    const int bx = idx & 3;
    const int by = (idx >> 2) & 3;
    const int b  = idx >> 4;
    const int t0 = by * 128;
    const int j0 = bx * 128;
    const int lane = tid & 31;
    const int warp_m = (tid >> 5) & 1;
    const int warp_n = tid >> 6;
    const uint32_t sbase = smem_to_u32(smem);

    {
        const uint32_t* gh = (const uint32_t*)(g_urh + (size_t)b * URPAD);
        uint32_t* sh = (uint32_t*)(smem + URS_OFF);
        for (int q = tid; q < 320; q += 256) sh[q] = gh[q];
    }
    __syncthreads();
    const uint32_t* ursh32 = (const uint32_t*)(smem + URS_OFF);

    const __half* xh = g_xh + ((size_t)(b * SEQ + t0)) * DIN;
    const __half* wt = g_wht + (size_t)j0 * DIN;
    const __half* gt = g_gt + (size_t)j0 * SEQ;

    const int nchunks = 10 + 2 * by;         // 8 dense + (2*by+2) toeplitz
    bool ready_seen = false;

    auto fill = [&](int i, int p) {
        uint32_t sb = sbase + p * BUFB;
        char* sc = smem + p * BUFB;
        if (i < 8) {
            int k0 = i * 64;
            cp_tile64(sb,         xh + k0, DIN, tid);
            cp_tile64(sb + TILEB, wt + k0, DIN, tid);
        } else {
            if (!ready_seen) {
                unsigned rdy;
                while (true) {
                    asm volatile("ld.global.acquire.gpu.b32 %0, [%1];" : "=r"(rdy) : "l"(&g_ready));
                    if (rdy) break;
                    __nanosleep(256);
                }
                ready_seen = true;
            }
            int d0 = (i - 8) * 64;
            cp_tile64(sb + TILEB, gt + d0, SEQ, tid);
            int r = tid >> 1, hf = tid & 1;
            int s0 = 511 - (t0 + r) + d0 + hf * 32;
            int base = s0 >> 1, par = s0 & 1;
            uint32_t w[16];
            uint32_t w0 = ursh32[base];
#pragma unroll
            for (int c = 0; c < 16; c++) {
                uint32_t w1 = ursh32[base + c + 1];
                w[c] = par ? __byte_perm(w0, w1, 0x5432) : w0;
                w0 = w1;
            }
#pragma unroll
            for (int q = 0; q < 4; q++)
                *(uint4*)(sc + r * RSB + hf * 64 + q * 16) =
                    make_uint4(w[q * 4], w[q * 4 + 1], w[q * 4 + 2], w[q * 4 + 3]);
        }
    };

    float acc[4][4][4];
#pragma unroll
    for (int mi = 0; mi < 4; mi++)
#pragma unroll
        for (int ni = 0; ni < 4; ni++)
#pragma unroll
            for (int e = 0; e < 4; e++) acc[mi][ni][e] = 0.f;

    fill(0, 0);
    CP_COMMIT();

    const uint32_t a_base_off = (warp_m * 64 + (lane & 15)) * RSB + ((lane >> 4) << 4);
    const uint32_t b_base_off = TILEB + (warp_n * 32 + (lane & 15)) * RSB + ((lane >> 4) << 4);

    for (int i = 0; i < nchunks; i++) {
        int p = i & 1;
        if (i + 1 < nchunks) { fill(i + 1, p ^ 1); CP_COMMIT(); CP_WAIT1(); }
        else CP_WAIT0();
        __syncthreads();

        uint32_t base = sbase + p * BUFB;
#pragma unroll
        for (int ks = 0; ks < 4; ks++) {
            uint32_t bh[4][2];
            {
                uint32_t r[4];
                uint32_t baddr = base + b_base_off + ks * 32;
                ldsm4(r, baddr);
                bh[0][0] = r[0]; bh[0][1] = r[2];
                bh[1][0] = r[1]; bh[1][1] = r[3];
                ldsm4(r, baddr + 16 * RSB);
                bh[2][0] = r[0]; bh[2][1] = r[2];
                bh[3][0] = r[1]; bh[3][1] = r[3];
            }
            uint32_t a[4][4];
            uint32_t aaddr = base + a_base_off + ks * 32;
#pragma unroll
            for (int mi = 0; mi < 4; mi++) ldsm4(a[mi], aaddr + mi * 16 * RSB);
#pragma unroll
            for (int mi = 0; mi < 4; mi++)
#pragma unroll
                for (int ni = 0; ni < 4; ni++)
                    mma_f16(acc[mi][ni], a[mi], bh[ni]);
        }
        __syncthreads();
    }

    // ---- epilogue ----
    const int g4 = lane >> 2, t4 = lane & 3;
    const size_t HN_BASE = (size_t)NBATCH * SEQ * HID;
    float2 bias[4];
#pragma unroll
    for (int ni = 0; ni < 4; ni++)
        bias[ni] = *(const float2*)(Whb + j0 + warp_n * 32 + ni * 8 + t4 * 2);
#pragma unroll
    for (int mi = 0; mi < 4; mi++) {
        int ta = t0 + warp_m * 64 + mi * 16 + g4;
        int tb = ta + 8;
        size_t rowa = ((size_t)b * SEQ + ta) * HID;
        size_t rowb = ((size_t)b * SEQ + tb) * HID;
#pragma unroll
        for (int ni = 0; ni < 4; ni++) {
            int j = j0 + warp_n * 32 + ni * 8 + t4 * 2;
            float2 v0, v1;
            v0.x = fmaxf(acc[mi][ni][0] + bias[ni].x, 0.f);
            v0.y = fmaxf(acc[mi][ni][1] + bias[ni].y, 0.f);
            v1.x = fmaxf(acc[mi][ni][2] + bias[ni].x, 0.f);
            v1.y = fmaxf(acc[mi][ni][3] + bias[ni].y, 0.f);
            *(float2*)(out + rowa + j) = v0;
            *(float2*)(out + rowb + j) = v1;
            if (write_hn && tb == SEQ - 1)
                *(float2*)(out + HN_BASE + (size_t)b * HID + j) = v1;
        }
    }
}

// ---------------- launch ----------------
extern "C" void kernel_launch(void* const* d_in, const int* in_sizes, int n_in,
                              void* d_out, int out_size) {
    const float* x    = (const float*)d_in[0];
    const float* Wu_w = (const float*)d_in[1];
    const float* Wu_b = (const float*)d_in[2];
    const float* Wh_w = (const float*)d_in[3];
    const float* Wh_b = (const float*)d_in[4];
    const float* A    = (const float*)d_in[5];
    const float* B    = (const float*)d_in[6];
    float* out = (float*)d_out;

    int write_hn = (out_size >= NBATCH * SEQ * HID + NBATCH * HID) ? 1 : 0;

    static int inited = 0;
    if (!inited) {
        cudaFuncSetAttribute(k_fused, cudaFuncAttributeMaxDynamicSharedMemorySize, SMEM_DYN);
        inited = 1;
    }

    k_ux<<<NBATCH * SEQ / 8 + 256, 256>>>(x, Wu_w, Wu_b, Wh_w);
    k_fused<<<FUSED_GRID, 256, SMEM_DYN>>>(Wh_w, A, B, Wh_b, out, write_hn);
}

// round 14
// speedup vs baseline: 1.2757x; 1.0853x over previous
#include <cuda_runtime.h>
#include <cuda_fp16.h>
#include <cstdint>

#define SEQ 512
#define DIN 512
#define MEM 256
#define HID 512
#define NBATCH 64
#define URPAD 640

#define RSB 144                  // row stride bytes: 64 fp16 = 128 B + 16 pad
#define TILEB (128 * RSB)        // 18432 B
#define BUFB (2 * TILEB)         // A, B tiles
#define URS_OFF (2 * BUFB)
#define SMEM_DYN (2 * BUFB + 1280)   // 75008 B (chain path needs 66048 <= this)

#define CHAIN_N 128
#define UXWT_N 512
#define MAIN_N 1024
#define FUSED_GRID (CHAIN_N + UXWT_N + MAIN_N)
#define XS_PITCH 260

// ---------------- static device scratch ----------------
__device__ __align__(16) __half g_xh[NBATCH * SEQ * DIN];
__device__ __align__(16) __half g_urh[NBATCH * URPAD];
__device__ __align__(16) __half g_wht[HID * DIN];    // Wht[j][k] = Wh[256+k][j]
__device__ __align__(16) __half g_gt[HID * SEQ];     // Gt[j][d] = G[d][j]
__device__ float g_Ht[SEQ * MEM];
__device__ float g_AT[2][MEM * MEM];
__device__ unsigned g_count;    // chain barrier arrivals
__device__ unsigned g_epoch;    // chain barrier epoch
__device__ unsigned g_ready;    // gt ready flag
__device__ unsigned g_ucount;   // uxwt completions
__device__ unsigned g_uready;   // u/x/wht ready flag

// ---------------- helpers ----------------
__device__ __forceinline__ uint32_t smem_to_u32(const void* p) {
    uint32_t a;
    asm("{ .reg .u64 t; cvta.to.shared.u64 t, %1; cvt.u32.u64 %0, t; }" : "=r"(a) : "l"(p));
    return a;
}
__device__ __forceinline__ void cp16(uint32_t dst, const void* src) {
    asm volatile("cp.async.cg.shared.global [%0], [%1], 16;" :: "r"(dst), "l"(src));
}
#define CP_COMMIT() asm volatile("cp.async.commit_group;" ::: "memory")
#define CP_WAIT0()  asm volatile("cp.async.wait_group 0;" ::: "memory")
#define CP_WAIT1()  asm volatile("cp.async.wait_group 1;" ::: "memory")

__device__ __forceinline__ void ldsm4(uint32_t r[4], uint32_t addr) {
    asm volatile("ldmatrix.sync.aligned.m8n8.x4.shared.b16 {%0,%1,%2,%3}, [%4];"
                 : "=r"(r[0]), "=r"(r[1]), "=r"(r[2]), "=r"(r[3]) : "r"(addr));
}
__device__ __forceinline__ void mma_f16(float* c, const uint32_t* a, const uint32_t* b) {
    asm volatile(
        "mma.sync.aligned.m16n8k16.row.col.f32.f16.f16.f32 "
        "{%0,%1,%2,%3}, {%4,%5,%6,%7}, {%8,%9}, {%0,%1,%2,%3};"
        : "+f"(c[0]), "+f"(c[1]), "+f"(c[2]), "+f"(c[3])
        : "r"(a[0]), "r"(a[1]), "r"(a[2]), "r"(a[3]), "r"(b[0]), "r"(b[1]));
}

__device__ __forceinline__ unsigned acq_load(const unsigned* p) {
    unsigned v;
    asm volatile("ld.global.acquire.gpu.b32 %0, [%1];" : "=r"(v) : "l"(p));
    return v;
}

// grid barrier among chain blocks: arrive via atomic, wait via acquire-load poll
__device__ __forceinline__ void grid_barrier(int bar) {
    __threadfence();
    __syncthreads();
    if (threadIdx.x == 0) {
        unsigned my = atomicAdd(&g_count, 1u);
        if (my == (unsigned)(CHAIN_N * bar - 1)) {
            atomicAdd(&g_epoch, 1u);
        } else {
            while (acq_load(&g_epoch) < (unsigned)bar) __nanosleep(64);
        }
    }
    __syncthreads();
}

// ---------------- k_reset: zero sync state before each replay ----------------
__global__ void k_reset() {
    g_count = 0; g_epoch = 0; g_ready = 0; g_ucount = 0; g_uready = 0;
}

// ---------------- chain path (blocks [0,128)) ----------------
__device__ void chain_path(char* smem, int bid, int tid,
                           const float* __restrict__ Wh,
                           const float* __restrict__ A,
                           const float* __restrict__ Bv) {
    float* Xs = (float*)smem;                  // [32][XS_PITCH]
    float* Bs = Xs + 32 * XS_PITCH;            // [256][32]
    const int ty = tid >> 4, tx = tid & 15;

    {
        int k0 = bid * 2;
#pragma unroll
        for (int h = 0; h < 2; h++)
            g_AT[0][(size_t)(k0 + h) * MEM + tid] = A[(size_t)tid * MEM + k0 + h];
        if (bid == 0) g_Ht[tid] = Bv[tid];
    }
    grid_barrier(1);

    for (int r = 0; r <= 8; r++) {
        int n = 1 << r;
        int sel = r & 1;
        int nsq = (r < 8) ? 64 : 0;
        int nrt = (n + 31) / 32;
        int ntiles = nsq + nrt * 8;
        const float* __restrict__ ATin = g_AT[sel];
        for (int t = bid; t < ntiles; t += CHAIN_N) {
            const float* Amat; float* Cmat; int rows, tr, tc;
            if (t < nsq) { Amat = ATin; Cmat = g_AT[sel ^ 1]; rows = MEM; tr = t >> 3; tc = t & 7; }
            else { int te = t - nsq; Amat = g_Ht; Cmat = g_Ht + (size_t)n * MEM; rows = n; tr = te >> 3; tc = te & 7; }
            int r0 = tr * 32, c0 = tc * 32;
            __syncthreads();
            for (int q = tid; q < 2048; q += 256) {
                int row = q >> 6, c4 = (q & 63) * 4;
                float4 v = make_float4(0.f, 0.f, 0.f, 0.f);
                if (r0 + row < rows) v = *(const float4*)(Amat + (size_t)(r0 + row) * MEM + c4);
                *(float4*)&Xs[row * XS_PITCH + c4] = v;
                int brow = q >> 3, bc4 = (q & 7) * 4;
                *(float4*)&Bs[brow * 32 + bc4] = *(const float4*)(ATin + (size_t)brow * MEM + c0 + bc4);
            }
            __syncthreads();
            float acc[2][2] = {};
#pragma unroll 8
            for (int k = 0; k < MEM; k++) {
                float a0 = Xs[(ty * 2) * XS_PITCH + k], a1 = Xs[(ty * 2 + 1) * XS_PITCH + k];
                float b0 = Bs[k * 32 + tx * 2],         b1 = Bs[k * 32 + tx * 2 + 1];
                acc[0][0] = fmaf(a0, b0, acc[0][0]); acc[0][1] = fmaf(a0, b1, acc[0][1]);
                acc[1][0] = fmaf(a1, b0, acc[1][0]); acc[1][1] = fmaf(a1, b1, acc[1][1]);
            }
#pragma unroll
            for (int i = 0; i < 2; i++) {
                int rr = r0 + ty * 2 + i;
                if (rr < rows) {
                    Cmat[(size_t)rr * MEM + c0 + tx * 2]     = acc[i][0];
                    Cmat[(size_t)rr * MEM + c0 + tx * 2 + 1] = acc[i][1];
                }
            }
        }
        grid_barrier(r + 2);
    }

    for (int t = bid; t < 256; t += CHAIN_N) {
        int tr = t >> 4, tc = t & 15;
        int d0 = tr * 32, j0 = tc * 32;
        __syncthreads();
        for (int q = tid; q < 2048; q += 256) {
            int row = q >> 6, c4 = (q & 63) * 4;
            *(float4*)&Xs[row * XS_PITCH + c4] = *(const float4*)(g_Ht + (size_t)(d0 + row) * MEM + c4);
            int brow = q >> 3, bc4 = (q & 7) * 4;
            *(float4*)&Bs[brow * 32 + bc4] = *(const float4*)(Wh + (size_t)brow * HID + j0 + bc4);
        }
        __syncthreads();
        float acc[2][2] = {};
#pragma unroll 8
        for (int k = 0; k < MEM; k++) {
            float a0 = Xs[(ty * 2) * XS_PITCH + k], a1 = Xs[(ty * 2 + 1) * XS_PITCH + k];
            float b0 = Bs[k * 32 + tx * 2],         b1 = Bs[k * 32 + tx * 2 + 1];
            acc[0][0] = fmaf(a0, b0, acc[0][0]); acc[0][1] = fmaf(a0, b1, acc[0][1]);
            acc[1][0] = fmaf(a1, b0, acc[1][0]); acc[1][1] = fmaf(a1, b1, acc[1][1]);
        }
#pragma unroll
        for (int i = 0; i < 2; i++)
#pragma unroll
            for (int jj = 0; jj < 2; jj++) {
                int d = d0 + ty * 2 + i, j = j0 + tx * 2 + jj;
                g_gt[(size_t)j * SEQ + d] = __float2half(acc[i][jj]);
            }
    }

    __threadfence();
    __syncthreads();
    if (tid == 0) {
        unsigned my = atomicAdd(&g_count, 1u);
        if (my == (unsigned)(CHAIN_N * 11 - 1))
            asm volatile("st.global.release.gpu.b32 [%0], %1;" :: "l"(&g_ready), "r"(1u) : "memory");
    }
}

// ---------------- uxwt path (blocks [128,640)) ----------------
__device__ void uxwt_path(char* smem, int idx, int tid,
                          const float* __restrict__ x,
                          const float* __restrict__ wu,
                          const float* __restrict__ wub,
                          const float* __restrict__ Wh) {
    int lane = tid & 31, w = tid >> 5;
    const float4* wr = (const float4*)wu;
    // ux: 64 rows per block (8 warps x 8 passes)
#pragma unroll 1
    for (int p = 0; p < 8; p++) {
        int row = idx * 64 + w * 8 + p;
        const float4* xr = (const float4*)(x + (size_t)row * DIN);
        float s = 0.f;
#pragma unroll
        for (int i = 0; i < 4; i++) {
            float4 v = xr[lane + 32 * i];
            float4 ww = wr[lane + 32 * i];
            s += v.x * ww.x + v.y * ww.y + v.z * ww.z + v.w * ww.w;
            size_t off = (size_t)row * DIN + (lane + 32 * i) * 4;
            __half2 ha = {__float2half(v.x), __float2half(v.y)};
            __half2 hb = {__float2half(v.z), __float2half(v.w)};
            *(__half2*)(g_xh + off) = ha; *(__half2*)(g_xh + off + 2) = hb;
        }
#pragma unroll
        for (int o = 16; o; o >>= 1) s += __shfl_xor_sync(0xffffffffu, s, o);
        if (lane == 0) {
            float u = fmaxf(s + wub[0], 0.f);
            int b = row >> 9, t = row & 511;
            g_urh[b * URPAD + (511 - t)] = __float2half(u);
            if (t < 128) g_urh[b * URPAD + 512 + t] = __float2half(0.f);
        }
    }
    // wt: first 256 blocks each transpose one 32x32 tile
    if (idx < 256) {
        float (*tile)[33] = (float (*)[33])smem;
        int kb = idx & 15, jb = idx >> 4;
        int tx = tid & 31, ty = tid >> 5;
        for (int yy = ty; yy < 32; yy += 8)
            tile[yy][tx] = Wh[(size_t)(MEM + kb * 32 + yy) * HID + jb * 32 + tx];
        __syncthreads();
        for (int yy = ty; yy < 32; yy += 8) {
            float v = tile[tx][yy];
            int j = jb * 32 + yy, k = kb * 32 + tx;
            g_wht[(size_t)j * DIN + k] = __float2half(v);
        }
    }
    // counted join -> release g_uready
    __threadfence();
    __syncthreads();
    if (tid == 0) {
        unsigned my = atomicAdd(&g_ucount, 1u);
        if (my == (unsigned)(UXWT_N - 1))
            asm volatile("st.global.release.gpu.b32 [%0], %1;" :: "l"(&g_uready), "r"(1u) : "memory");
    }
}

// ---------------- fused kernel ----------------
__device__ __forceinline__ void cp_tile64(uint32_t sdst, const __half* __restrict__ g,
                                          int stride, int tid) {
#pragma unroll
    for (int it = 0; it < 4; it++) {
        int q = tid + it * 256;
        int row = q >> 3, ch = q & 7;
        cp16(sdst + row * RSB + ch * 16, g + (size_t)row * stride + ch * 8);
    }
}

__global__ __launch_bounds__(256, 2) void k_all(const float* __restrict__ x,
                                                const float* __restrict__ wu,
                                                const float* __restrict__ wub,
                                                const float* __restrict__ Wh,
                                                const float* __restrict__ A,
                                                const float* __restrict__ Bv,
                                                const float* __restrict__ Whb,
                                                float* __restrict__ out, int write_hn) {
    extern __shared__ __align__(128) char smem[];
    const int gbid = blockIdx.x;
    const int tid = threadIdx.x;

    if (gbid < CHAIN_N) { chain_path(smem, gbid, tid, Wh, A, Bv); return; }
    if (gbid < CHAIN_N + UXWT_N) { uxwt_path(smem, gbid - CHAIN_N, tid, x, wu, wub, Wh); return; }

    // ---------------- main GEMM path ----------------
    const int idx = gbid - CHAIN_N - UXWT_N;   // [0,1024)
    const int bx = idx & 3;
    const int by = (idx >> 2) & 3;
    const int b  = idx >> 4;
    const int t0 = by * 128;
    const int j0 = bx * 128;
    const int lane = tid & 31;
    const int warp_m = (tid >> 5) & 1;
    const int warp_n = tid >> 6;
    const uint32_t sbase = smem_to_u32(smem);

    // wait for u/x/wht producers
    if (tid == 0) {
        while (!acq_load(&g_uready)) __nanosleep(256);
    }
    __syncthreads();

    {
        const uint32_t* gh = (const uint32_t*)(g_urh + (size_t)b * URPAD);
        uint32_t* sh = (uint32_t*)(smem + URS_OFF);
        for (int q = tid; q < 320; q += 256) sh[q] = gh[q];
    }
    __syncthreads();
    const uint32_t* ursh32 = (const uint32_t*)(smem + URS_OFF);

    const __half* xh = g_xh + ((size_t)(b * SEQ + t0)) * DIN;
    const __half* wt = g_wht + (size_t)j0 * DIN;
    const __half* gt = g_gt + (size_t)j0 * SEQ;

    const int nchunks = 10 + 2 * by;
    bool ready_seen = false;

    auto fill = [&](int i, int p) {
        uint32_t sb = sbase + p * BUFB;
        char* sc = smem + p * BUFB;
        if (i < 8) {
            int k0 = i * 64;
            cp_tile64(sb,         xh + k0, DIN, tid);
            cp_tile64(sb + TILEB, wt + k0, DIN, tid);
        } else {
            if (!ready_seen) {
                while (!acq_load(&g_ready)) __nanosleep(256);
                ready_seen = true;
            }
            int d0 = (i - 8) * 64;
            cp_tile64(sb + TILEB, gt + d0, SEQ, tid);
            int r = tid >> 1, hf = tid & 1;
            int s0 = 511 - (t0 + r) + d0 + hf * 32;
            int base = s0 >> 1, par = s0 & 1;
            uint32_t w[16];
            uint32_t w0 = ursh32[base];
#pragma unroll
            for (int c = 0; c < 16; c++) {
                uint32_t w1 = ursh32[base + c + 1];
                w[c] = par ? __byte_perm(w0, w1, 0x5432) : w0;
                w0 = w1;
            }
#pragma unroll
            for (int q = 0; q < 4; q++)
                *(uint4*)(sc + r * RSB + hf * 64 + q * 16) =
                    make_uint4(w[q * 4], w[q * 4 + 1], w[q * 4 + 2], w[q * 4 + 3]);
        }
    };

    float acc[4][4][4];
#pragma unroll
    for (int mi = 0; mi < 4; mi++)
#pragma unroll
        for (int ni = 0; ni < 4; ni++)
#pragma unroll
            for (int e = 0; e < 4; e++) acc[mi][ni][e] = 0.f;

    fill(0, 0);
    CP_COMMIT();

    const uint32_t a_base_off = (warp_m * 64 + (lane & 15)) * RSB + ((lane >> 4) << 4);
    const uint32_t b_base_off = TILEB + (warp_n * 32 + (lane & 15)) * RSB + ((lane >> 4) << 4);

    for (int i = 0; i < nchunks; i++) {
        int p = i & 1;
        if (i + 1 < nchunks) { fill(i + 1, p ^ 1); CP_COMMIT(); CP_WAIT1(); }
        else CP_WAIT0();
        __syncthreads();

        uint32_t base = sbase + p * BUFB;
#pragma unroll
        for (int ks = 0; ks < 4; ks++) {
            uint32_t bh[4][2];
            {
                uint32_t r[4];
                uint32_t baddr = base + b_base_off + ks * 32;
                ldsm4(r, baddr);
                bh[0][0] = r[0]; bh[0][1] = r[2];
                bh[1][0] = r[1]; bh[1][1] = r[3];
                ldsm4(r, baddr + 16 * RSB);
                bh[2][0] = r[0]; bh[2][1] = r[2];
                bh[3][0] = r[1]; bh[3][1] = r[3];
            }
            uint32_t a[4][4];
            uint32_t aaddr = base + a_base_off + ks * 32;
#pragma unroll
            for (int mi = 0; mi < 4; mi++) ldsm4(a[mi], aaddr + mi * 16 * RSB);
#pragma unroll
            for (int mi = 0; mi < 4; mi++)
#pragma unroll
                for (int ni = 0; ni < 4; ni++)
                    mma_f16(acc[mi][ni], a[mi], bh[ni]);
        }
        __syncthreads();
    }

    // ---- epilogue ----
    const int g4 = lane >> 2, t4 = lane & 3;
    const size_t HN_BASE = (size_t)NBATCH * SEQ * HID;
    float2 bias[4];
#pragma unroll
    for (int ni = 0; ni < 4; ni++)
        bias[ni] = *(const float2*)(Whb + j0 + warp_n * 32 + ni * 8 + t4 * 2);
#pragma unroll
    for (int mi = 0; mi < 4; mi++) {
        int ta = t0 + warp_m * 64 + mi * 16 + g4;
        int tb = ta + 8;
        size_t rowa = ((size_t)b * SEQ + ta) * HID;
        size_t rowb = ((size_t)b * SEQ + tb) * HID;
#pragma unroll
        for (int ni = 0; ni < 4; ni++) {
            int j = j0 + warp_n * 32 + ni * 8 + t4 * 2;
            float2 v0, v1;
            v0.x = fmaxf(acc[mi][ni][0] + bias[ni].x, 0.f);
            v0.y = fmaxf(acc[mi][ni][1] + bias[ni].y, 0.f);
            v1.x = fmaxf(acc[mi][ni][2] + bias[ni].x, 0.f);
            v1.y = fmaxf(acc[mi][ni][3] + bias[ni].y, 0.f);
            *(float2*)(out + rowa + j) = v0;
            *(float2*)(out + rowb + j) = v1;
            if (write_hn && tb == SEQ - 1)
                *(float2*)(out + HN_BASE + (size_t)b * HID + j) = v1;
        }
    }
}

// ---------------- launch ----------------
extern "C" void kernel_launch(void* const* d_in, const int* in_sizes, int n_in,
                              void* d_out, int out_size) {
    const float* x    = (const float*)d_in[0];
    const float* Wu_w = (const float*)d_in[1];
    const float* Wu_b = (const float*)d_in[2];
    const float* Wh_w = (const float*)d_in[3];
    const float* Wh_b = (const float*)d_in[4];
    const float* A    = (const float*)d_in[5];
    const float* B    = (const float*)d_in[6];
    float* out = (float*)d_out;

    int write_hn = (out_size >= NBATCH * SEQ * HID + NBATCH * HID) ? 1 : 0;

    static int inited = 0;
    if (!inited) {
        cudaFuncSetAttribute(k_all, cudaFuncAttributeMaxDynamicSharedMemorySize, SMEM_DYN);
        inited = 1;
    }

    k_reset<<<1, 1>>>();
    k_all<<<FUSED_GRID, 256, SMEM_DYN>>>(x, Wu_w, Wu_b, Wh_w, A, B, Wh_b, out, write_hn);
}

// round 15
// speedup vs baseline: 1.2776x; 1.0015x over previous
#include <cuda_runtime.h>
#include <cuda_fp16.h>
#include <cstdint>

#define SEQ 512
#define DIN 512
#define MEM 256
#define HID 512
#define NBATCH 64
#define URPAD 640

#define RSB 144                  // row stride bytes: 64 fp16 = 128 B + 16 pad
#define TILEB (128 * RSB)        // 18432 B
#define BUFB (2 * TILEB)         // A, B tiles
#define URS_OFF (2 * BUFB)
#define SMEM_DYN (2 * BUFB + 1280)   // 75008 B (chain path needs 66048 <= this)

#define CHAIN_N 128
#define WT_N 256
#define UX_N 1024
#define MAIN_N 1024
#define FUSED_GRID (CHAIN_N + WT_N + UX_N + MAIN_N)
#define XS_PITCH 260

// ---------------- static device scratch ----------------
__device__ __align__(16) __half g_xh[NBATCH * SEQ * DIN];
__device__ __align__(16) __half g_urh[NBATCH * URPAD];
__device__ __align__(16) __half g_wht[HID * DIN];    // Wht[j][k] = Wh[256+k][j]
__device__ __align__(16) __half g_gt[HID * SEQ];     // Gt[j][d] = G[d][j]
__device__ float g_Ht[SEQ * MEM];
__device__ float g_AT[2][MEM * MEM];
__device__ unsigned g_count;          // chain barrier arrivals
__device__ unsigned g_epoch;          // chain barrier epoch
__device__ unsigned g_ready;          // gt ready flag
__device__ unsigned g_wcount;         // wt completions
__device__ unsigned g_wflag;          // wht ready
__device__ unsigned g_ucnt[NBATCH];   // per-batch ux completions
__device__ unsigned g_uflag[NBATCH];  // per-batch ux ready

// ---------------- helpers ----------------
__device__ __forceinline__ uint32_t smem_to_u32(const void* p) {
    uint32_t a;
    asm("{ .reg .u64 t; cvta.to.shared.u64 t, %1; cvt.u32.u64 %0, t; }" : "=r"(a) : "l"(p));
    return a;
}
__device__ __forceinline__ void cp16(uint32_t dst, const void* src) {
    asm volatile("cp.async.cg.shared.global [%0], [%1], 16;" :: "r"(dst), "l"(src));
}
#define CP_COMMIT() asm volatile("cp.async.commit_group;" ::: "memory")
#define CP_WAIT0()  asm volatile("cp.async.wait_group 0;" ::: "memory")
#define CP_WAIT1()  asm volatile("cp.async.wait_group 1;" ::: "memory")

__device__ __forceinline__ void ldsm4(uint32_t r[4], uint32_t addr) {
    asm volatile("ldmatrix.sync.aligned.m8n8.x4.shared.b16 {%0,%1,%2,%3}, [%4];"
                 : "=r"(r[0]), "=r"(r[1]), "=r"(r[2]), "=r"(r[3]) : "r"(addr));
}
__device__ __forceinline__ void mma_f16(float* c, const uint32_t* a, const uint32_t* b) {
    asm volatile(
        "mma.sync.aligned.m16n8k16.row.col.f32.f16.f16.f32 "
        "{%0,%1,%2,%3}, {%4,%5,%6,%7}, {%8,%9}, {%0,%1,%2,%3};"
        : "+f"(c[0]), "+f"(c[1]), "+f"(c[2]), "+f"(c[3])
        : "r"(a[0]), "r"(a[1]), "r"(a[2]), "r"(a[3]), "r"(b[0]), "r"(b[1]));
}

__device__ __forceinline__ unsigned acq_load(const unsigned* p) {
    unsigned v;
    asm volatile("ld.global.acquire.gpu.b32 %0, [%1];" : "=r"(v) : "l"(p));
    return v;
}
__device__ __forceinline__ void rel_store(unsigned* p, unsigned v) {
    asm volatile("st.global.release.gpu.b32 [%0], %1;" :: "l"(p), "r"(v) : "memory");
}

// grid barrier among chain blocks
__device__ __forceinline__ void grid_barrier(int bar) {
    __threadfence();
    __syncthreads();
    if (threadIdx.x == 0) {
        unsigned my = atomicAdd(&g_count, 1u);
        if (my == (unsigned)(CHAIN_N * bar - 1)) {
            atomicAdd(&g_epoch, 1u);
        } else {
            while (acq_load(&g_epoch) < (unsigned)bar) __nanosleep(64);
        }
    }
    __syncthreads();
}

// ---------------- k_reset: zero sync state before each replay ----------------
__global__ void k_reset() {
    int t = threadIdx.x;
    if (t == 0) { g_count = 0; g_epoch = 0; g_ready = 0; g_wcount = 0; g_wflag = 0; }
    if (t < NBATCH) { g_ucnt[t] = 0; g_uflag[t] = 0; }
}

// ---------------- chain path (blocks [0,128)) ----------------
__device__ void chain_path(char* smem, int bid, int tid,
                           const float* __restrict__ Wh,
                           const float* __restrict__ A,
                           const float* __restrict__ Bv) {
    float* Xs = (float*)smem;                  // [32][XS_PITCH]
    float* Bs = Xs + 32 * XS_PITCH;            // [256][32]
    const int ty = tid >> 4, tx = tid & 15;

    {
        int k0 = bid * 2;
#pragma unroll
        for (int h = 0; h < 2; h++)
            g_AT[0][(size_t)(k0 + h) * MEM + tid] = A[(size_t)tid * MEM + k0 + h];
        if (bid == 0) g_Ht[tid] = Bv[tid];
    }
    grid_barrier(1);

    for (int r = 0; r <= 8; r++) {
        int n = 1 << r;
        int sel = r & 1;
        int nsq = (r < 8) ? 64 : 0;
        int nrt = (n + 31) / 32;
        int ntiles = nsq + nrt * 8;
        const float* __restrict__ ATin = g_AT[sel];
        for (int t = bid; t < ntiles; t += CHAIN_N) {
            const float* Amat; float* Cmat; int rows, tr, tc;
            if (t < nsq) { Amat = ATin; Cmat = g_AT[sel ^ 1]; rows = MEM; tr = t >> 3; tc = t & 7; }
            else { int te = t - nsq; Amat = g_Ht; Cmat = g_Ht + (size_t)n * MEM; rows = n; tr = te >> 3; tc = te & 7; }
            int r0 = tr * 32, c0 = tc * 32;
            __syncthreads();
            for (int q = tid; q < 2048; q += 256) {
                int row = q >> 6, c4 = (q & 63) * 4;
                float4 v = make_float4(0.f, 0.f, 0.f, 0.f);
                if (r0 + row < rows) v = *(const float4*)(Amat + (size_t)(r0 + row) * MEM + c4);
                *(float4*)&Xs[row * XS_PITCH + c4] = v;
                int brow = q >> 3, bc4 = (q & 7) * 4;
                *(float4*)&Bs[brow * 32 + bc4] = *(const float4*)(ATin + (size_t)brow * MEM + c0 + bc4);
            }
            __syncthreads();
            float acc[2][2] = {};
#pragma unroll 8
            for (int k = 0; k < MEM; k++) {
                float a0 = Xs[(ty * 2) * XS_PITCH + k], a1 = Xs[(ty * 2 + 1) * XS_PITCH + k];
                float b0 = Bs[k * 32 + tx * 2],         b1 = Bs[k * 32 + tx * 2 + 1];
                acc[0][0] = fmaf(a0, b0, acc[0][0]); acc[0][1] = fmaf(a0, b1, acc[0][1]);
                acc[1][0] = fmaf(a1, b0, acc[1][0]); acc[1][1] = fmaf(a1, b1, acc[1][1]);
            }
#pragma unroll
            for (int i = 0; i < 2; i++) {
                int rr = r0 + ty * 2 + i;
                if (rr < rows) {
                    Cmat[(size_t)rr * MEM + c0 + tx * 2]     = acc[i][0];
                    Cmat[(size_t)rr * MEM + c0 + tx * 2 + 1] = acc[i][1];
                }
            }
        }
        grid_barrier(r + 2);
    }

    for (int t = bid; t < 256; t += CHAIN_N) {
        int tr = t >> 4, tc = t & 15;
        int d0 = tr * 32, j0 = tc * 32;
        __syncthreads();
        for (int q = tid; q < 2048; q += 256) {
            int row = q >> 6, c4 = (q & 63) * 4;
            *(float4*)&Xs[row * XS_PITCH + c4] = *(const float4*)(g_Ht + (size_t)(d0 + row) * MEM + c4);
            int brow = q >> 3, bc4 = (q & 7) * 4;
            *(float4*)&Bs[brow * 32 + bc4] = *(const float4*)(Wh + (size_t)brow * HID + j0 + bc4);
        }
        __syncthreads();
        float acc[2][2] = {};
#pragma unroll 8
        for (int k = 0; k < MEM; k++) {
            float a0 = Xs[(ty * 2) * XS_PITCH + k], a1 = Xs[(ty * 2 + 1) * XS_PITCH + k];
            float b0 = Bs[k * 32 + tx * 2],         b1 = Bs[k * 32 + tx * 2 + 1];
            acc[0][0] = fmaf(a0, b0, acc[0][0]); acc[0][1] = fmaf(a0, b1, acc[0][1]);
            acc[1][0] = fmaf(a1, b0, acc[1][0]); acc[1][1] = fmaf(a1, b1, acc[1][1]);
        }
#pragma unroll
        for (int i = 0; i < 2; i++)
#pragma unroll
            for (int jj = 0; jj < 2; jj++) {
                int d = d0 + ty * 2 + i, j = j0 + tx * 2 + jj;
                g_gt[(size_t)j * SEQ + d] = __float2half(acc[i][jj]);
            }
    }

    __threadfence();
    __syncthreads();
    if (tid == 0) {
        unsigned my = atomicAdd(&g_count, 1u);
        if (my == (unsigned)(CHAIN_N * 11 - 1))
            rel_store(&g_ready, 1u);
    }
}

// ---------------- wt path (blocks [128,384)) ----------------
__device__ void wt_path(char* smem, int idx, int tid, const float* __restrict__ Wh) {
    float (*tile)[33] = (float (*)[33])smem;
    int kb = idx & 15, jb = idx >> 4;
    int tx = tid & 31, ty = tid >> 5;
    for (int yy = ty; yy < 32; yy += 8)
        tile[yy][tx] = Wh[(size_t)(MEM + kb * 32 + yy) * HID + jb * 32 + tx];
    __syncthreads();
    for (int yy = ty; yy < 32; yy += 8) {
        float v = tile[tx][yy];
        int j = jb * 32 + yy, k = kb * 32 + tx;
        g_wht[(size_t)j * DIN + k] = __float2half(v);
    }
    __threadfence();
    __syncthreads();
    if (tid == 0) {
        unsigned my = atomicAdd(&g_wcount, 1u);
        if (my == (unsigned)(WT_N - 1)) rel_store(&g_wflag, 1u);
    }
}

// ---------------- ux path (blocks [384,1408)): 32 rows/block ----------------
__device__ void ux_path(int idx, int tid,
                        const float* __restrict__ x,
                        const float* __restrict__ wu,
                        const float* __restrict__ wub) {
    int lane = tid & 31, w = tid >> 5;
    const float4* wr = (const float4*)wu;
#pragma unroll 1
    for (int p = 0; p < 4; p++) {
        int row = idx * 32 + w * 4 + p;
        const float4* xr = (const float4*)(x + (size_t)row * DIN);
        float s = 0.f;
#pragma unroll
        for (int i = 0; i < 4; i++) {
            float4 v = xr[lane + 32 * i];
            float4 ww = wr[lane + 32 * i];
            s += v.x * ww.x + v.y * ww.y + v.z * ww.z + v.w * ww.w;
            size_t off = (size_t)row * DIN + (lane + 32 * i) * 4;
            __half2 ha = {__float2half(v.x), __float2half(v.y)};
            __half2 hb = {__float2half(v.z), __float2half(v.w)};
            *(__half2*)(g_xh + off) = ha; *(__half2*)(g_xh + off + 2) = hb;
        }
#pragma unroll
        for (int o = 16; o; o >>= 1) s += __shfl_xor_sync(0xffffffffu, s, o);
        if (lane == 0) {
            float u = fmaxf(s + wub[0], 0.f);
            int b = row >> 9, t = row & 511;
            g_urh[b * URPAD + (511 - t)] = __float2half(u);
            if (t < 128) g_urh[b * URPAD + 512 + t] = __float2half(0.f);
        }
    }
    __threadfence();
    __syncthreads();
    if (tid == 0) {
        int b = idx >> 4;                         // 16 blocks per batch
        unsigned my = atomicAdd(&g_ucnt[b], 1u);
        if (my == 15u) rel_store(&g_uflag[b], 1u);
    }
}

// ---------------- fused kernel ----------------
__device__ __forceinline__ void cp_tile64(uint32_t sdst, const __half* __restrict__ g,
                                          int stride, int tid) {
#pragma unroll
    for (int it = 0; it < 4; it++) {
        int q = tid + it * 256;
        int row = q >> 3, ch = q & 7;
        cp16(sdst + row * RSB + ch * 16, g + (size_t)row * stride + ch * 8);
    }
}

__global__ __launch_bounds__(256, 2) void k_all(const float* __restrict__ x,
                                                const float* __restrict__ wu,
                                                const float* __restrict__ wub,
                                                const float* __restrict__ Wh,
                                                const float* __restrict__ A,
                                                const float* __restrict__ Bv,
                                                const float* __restrict__ Whb,
                                                float* __restrict__ out, int write_hn) {
    extern __shared__ __align__(128) char smem[];
    const int gbid = blockIdx.x;
    const int tid = threadIdx.x;

    if (gbid < CHAIN_N) { chain_path(smem, gbid, tid, Wh, A, Bv); return; }
    if (gbid < CHAIN_N + WT_N) { wt_path(smem, gbid - CHAIN_N, tid, Wh); return; }
    if (gbid < CHAIN_N + WT_N + UX_N) { ux_path(gbid - CHAIN_N - WT_N, tid, x, wu, wub); return; }

    // ---------------- main GEMM path ----------------
    const int idx = gbid - CHAIN_N - WT_N - UX_N;   // [0,1024)
    const int bx = idx & 3;
    const int by = 3 - ((idx >> 2) & 3);            // longest tiles first
    const int b  = idx >> 4;
    const int t0 = by * 128;
    const int j0 = bx * 128;
    const int lane = tid & 31;
    const int warp_m = (tid >> 5) & 1;
    const int warp_n = tid >> 6;
    const uint32_t sbase = smem_to_u32(smem);

    // wait for this batch's ux rows and the wht transpose
    if (tid == 0) {
        while (!acq_load(&g_uflag[b])) __nanosleep(128);
        while (!acq_load(&g_wflag)) __nanosleep(128);
    }
    __syncthreads();

    {
        const uint32_t* gh = (const uint32_t*)(g_urh + (size_t)b * URPAD);
        uint32_t* sh = (uint32_t*)(smem + URS_OFF);
        for (int q = tid; q < 320; q += 256) sh[q] = gh[q];
    }
    __syncthreads();
    const uint32_t* ursh32 = (const uint32_t*)(smem + URS_OFF);

    const __half* xh = g_xh + ((size_t)(b * SEQ + t0)) * DIN;
    const __half* wt = g_wht + (size_t)j0 * DIN;
    const __half* gt = g_gt + (size_t)j0 * SEQ;

    const int nchunks = 10 + 2 * by;
    bool ready_seen = false;

    auto fill = [&](int i, int p) {
        uint32_t sb = sbase + p * BUFB;
        char* sc = smem + p * BUFB;
        if (i < 8) {
            int k0 = i * 64;
            cp_tile64(sb,         xh + k0, DIN, tid);
            cp_tile64(sb + TILEB, wt + k0, DIN, tid);
        } else {
            if (!ready_seen) {
                while (!acq_load(&g_ready)) __nanosleep(256);
                ready_seen = true;
            }
            int d0 = (i - 8) * 64;
            cp_tile64(sb + TILEB, gt + d0, SEQ, tid);
            int r = tid >> 1, hf = tid & 1;
            int s0 = 511 - (t0 + r) + d0 + hf * 32;
            int base = s0 >> 1, par = s0 & 1;
            uint32_t w[16];
            uint32_t w0 = ursh32[base];
#pragma unroll
            for (int c = 0; c < 16; c++) {
                uint32_t w1 = ursh32[base + c + 1];
                w[c] = par ? __byte_perm(w0, w1, 0x5432) : w0;
                w0 = w1;
            }
#pragma unroll
            for (int q = 0; q < 4; q++)
                *(uint4*)(sc + r * RSB + hf * 64 + q * 16) =
                    make_uint4(w[q * 4], w[q * 4 + 1], w[q * 4 + 2], w[q * 4 + 3]);
        }
    };

    float acc[4][4][4];
#pragma unroll
    for (int mi = 0; mi < 4; mi++)
#pragma unroll
        for (int ni = 0; ni < 4; ni++)
#pragma unroll
            for (int e = 0; e < 4; e++) acc[mi][ni][e] = 0.f;

    fill(0, 0);
    CP_COMMIT();

    const uint32_t a_base_off = (warp_m * 64 + (lane & 15)) * RSB + ((lane >> 4) << 4);
    const uint32_t b_base_off = TILEB + (warp_n * 32 + (lane & 15)) * RSB + ((lane >> 4) << 4);

    for (int i = 0; i < nchunks; i++) {
        int p = i & 1;
        if (i + 1 < nchunks) { fill(i + 1, p ^ 1); CP_COMMIT(); CP_WAIT1(); }
        else CP_WAIT0();
        __syncthreads();

        uint32_t base = sbase + p * BUFB;
#pragma unroll
        for (int ks = 0; ks < 4; ks++) {
            uint32_t bh[4][2];
            {
                uint32_t r[4];
                uint32_t baddr = base + b_base_off + ks * 32;
                ldsm4(r, baddr);
                bh[0][0] = r[0]; bh[0][1] = r[2];
                bh[1][0] = r[1]; bh[1][1] = r[3];
                ldsm4(r, baddr + 16 * RSB);
                bh[2][0] = r[0]; bh[2][1] = r[2];
                bh[3][0] = r[1]; bh[3][1] = r[3];
            }
            uint32_t a[4][4];
            uint32_t aaddr = base + a_base_off + ks * 32;
#pragma unroll
            for (int mi = 0; mi < 4; mi++) ldsm4(a[mi], aaddr + mi * 16 * RSB);
#pragma unroll
            for (int mi = 0; mi < 4; mi++)
#pragma unroll
                for (int ni = 0; ni < 4; ni++)
                    mma_f16(acc[mi][ni], a[mi], bh[ni]);
        }
        __syncthreads();
    }

    // ---- epilogue ----
    const int g4 = lane >> 2, t4 = lane & 3;
    const size_t HN_BASE = (size_t)NBATCH * SEQ * HID;
    float2 bias[4];
#pragma unroll
    for (int ni = 0; ni < 4; ni++)
        bias[ni] = *(const float2*)(Whb + j0 + warp_n * 32 + ni * 8 + t4 * 2);
#pragma unroll
    for (int mi = 0; mi < 4; mi++) {
        int ta = t0 + warp_m * 64 + mi * 16 + g4;
        int tb = ta + 8;
        size_t rowa = ((size_t)b * SEQ + ta) * HID;
        size_t rowb = ((size_t)b * SEQ + tb) * HID;
#pragma unroll
        for (int ni = 0; ni < 4; ni++) {
            int j = j0 + warp_n * 32 + ni * 8 + t4 * 2;
            float2 v0, v1;
            v0.x = fmaxf(acc[mi][ni][0] + bias[ni].x, 0.f);
            v0.y = fmaxf(acc[mi][ni][1] + bias[ni].y, 0.f);
            v1.x = fmaxf(acc[mi][ni][2] + bias[ni].x, 0.f);
            v1.y = fmaxf(acc[mi][ni][3] + bias[ni].y, 0.f);
            *(float2*)(out + rowa + j) = v0;
            *(float2*)(out + rowb + j) = v1;
            if (write_hn && tb == SEQ - 1)
                *(float2*)(out + HN_BASE + (size_t)b * HID + j) = v1;
        }
    }
}

// ---------------- launch ----------------
extern "C" void kernel_launch(void* const* d_in, const int* in_sizes, int n_in,
                              void* d_out, int out_size) {
    const float* x    = (const float*)d_in[0];
    const float* Wu_w = (const float*)d_in[1];
    const float* Wu_b = (const float*)d_in[2];
    const float* Wh_w = (const float*)d_in[3];
    const float* Wh_b = (const float*)d_in[4];
    const float* A    = (const float*)d_in[5];
    const float* B    = (const float*)d_in[6];
    float* out = (float*)d_out;

    int write_hn = (out_size >= NBATCH * SEQ * HID + NBATCH * HID) ? 1 : 0;

    static int inited = 0;
    if (!inited) {
        cudaFuncSetAttribute(k_all, cudaFuncAttributeMaxDynamicSharedMemorySize, SMEM_DYN);
        inited = 1;
    }

    k_reset<<<1, 256>>>();
    k_all<<<FUSED_GRID, 256, SMEM_DYN>>>(x, Wu_w, Wu_b, Wh_w, A, B, Wh_b, out, write_hn);
}